// round 3
// baseline (speedup 1.0000x reference)
#include <cuda_runtime.h>
#include <math.h>
#include <stdint.h>

#define BB 64
#define UU 512
#define EMBD 256
#define NS 32
#define NW 50
#define VV 50000
#define EXT 50100

// d_out layout: [dec 64*512][gen 64*50100][copy 64*50100][p_gen 64]
#define GEN_OFF   ((size_t)BB*UU)
#define COPY_OFF  (GEN_OFF + (size_t)BB*EXT)
#define PGEN_OFF  (COPY_OFF + (size_t)BB*EXT)

// ------------- scratch (no allocations allowed) -------------
__device__ float g_xm[BB*1536];
__device__ float g_hm[BB*1536];
__device__ float g_q[BB*UU];
__device__ float g_qw[BB*UU];
__device__ float g_alpha[BB*NS];
__device__ float g_ctx[BB*UU];
__device__ float g_htp[BB*256];   // dec @ wd_bot partial
__device__ float g_ht[BB*256];
__device__ float g_rowsum[BB];

// ------------- helpers -------------
__device__ __forceinline__ uint32_t f2tf32(float f) {
    uint32_t u;
    asm("cvt.rna.tf32.f32 %0, %1;" : "=r"(u) : "f"(f));
    return u;
}

__device__ __forceinline__ void mma_tf32(float& c0, float& c1, float& c2, float& c3,
                                         uint32_t a0, uint32_t a1, uint32_t a2, uint32_t a3,
                                         uint32_t b0, uint32_t b1) {
    asm volatile(
        "mma.sync.aligned.m16n8k8.row.col.f32.tf32.tf32.f32 "
        "{%0,%1,%2,%3}, {%4,%5,%6,%7}, {%8,%9}, {%0,%1,%2,%3};\n"
        : "+f"(c0), "+f"(c1), "+f"(c2), "+f"(c3)
        : "r"(a0), "r"(a1), "r"(a2), "r"(a3), "r"(b0), "r"(b1));
}

// ------------- init: zero copy region, gen padding, rowsums -------------
__global__ __launch_bounds__(256) void k_init(float* __restrict__ out) {
    size_t i = (size_t)blockIdx.x * blockDim.x + threadIdx.x;
    size_t total = (size_t)BB * EXT;
    size_t stride = (size_t)gridDim.x * blockDim.x;
    for (size_t t = i; t < total; t += stride) {
        out[COPY_OFF + t] = 0.0f;
        int v = (int)(t % EXT);
        if (v >= VV) out[GEN_OFF + t] = 0.0f;
    }
    if (i < BB) g_rowsum[i] = 0.0f;
}

// ------------- small GEMM tile: C[64, 32-col tile] = A[64,K] @ W[K,N] -------------
__device__ __forceinline__ void gemm_tile(float* As, float* Wt,
                                          const float* __restrict__ A,
                                          const float* __restrict__ W,
                                          const float* __restrict__ bias,
                                          const float* __restrict__ addend,
                                          float* __restrict__ C,
                                          int K, int N, int blk, int act) {
    int tid = threadIdx.x;
    int c  = tid & 31;
    int rg = tid >> 5;            // 8 row groups of 8 rows
    int n0 = blk * 32;
    int n  = n0 + c;

    float acc[8];
#pragma unroll
    for (int r = 0; r < 8; r++) acc[r] = 0.0f;

    for (int k0 = 0; k0 < K; k0 += 32) {
        for (int i = tid; i < 2048; i += 256) {
            int k = i & 31, b = i >> 5;
            As[k * 68 + b] = A[(size_t)b * K + k0 + k];
        }
        for (int i = tid; i < 1024; i += 256) {
            int kk = i >> 5, c2 = i & 31;
            Wt[kk * 32 + c2] = W[(size_t)(k0 + kk) * N + n0 + c2];
        }
        __syncthreads();
#pragma unroll 8
        for (int kk = 0; kk < 32; kk++) {
            float w = Wt[kk * 32 + c];
            float4 a0 = *(const float4*)&As[kk * 68 + rg * 8];
            float4 a1 = *(const float4*)&As[kk * 68 + rg * 8 + 4];
            acc[0] += a0.x * w; acc[1] += a0.y * w;
            acc[2] += a0.z * w; acc[3] += a0.w * w;
            acc[4] += a1.x * w; acc[5] += a1.y * w;
            acc[6] += a1.z * w; acc[7] += a1.w * w;
        }
        __syncthreads();
    }
    float bv = bias ? bias[n] : 0.0f;
#pragma unroll
    for (int r = 0; r < 8; r++) {
        int row = rg * 8 + r;
        float v = acc[r] + bv;
        if (addend) v += addend[(size_t)row * N + n];
        if (act == 1) v = tanhf(v);
        C[(size_t)row * N + n] = v;
    }
}

// ------------- fused GRU gate GEMMs: blocks 0-47 xm, 48-95 hm -------------
__global__ __launch_bounds__(256) void k_gates(const float* __restrict__ emb,
                                               const float* __restrict__ Wx,
                                               const float* __restrict__ hid,
                                               const float* __restrict__ Wh,
                                               const float* __restrict__ gb,
                                               float* __restrict__ xm,
                                               float* __restrict__ hm) {
    __shared__ __align__(16) float As[32 * 68];
    __shared__ __align__(16) float Wt[32 * 32];
    const float* A; const float* W; const float* b; float* C; int K; int blk;
    if (blockIdx.x < 48) { A = emb; W = Wx; b = gb;        C = xm; K = 256; blk = blockIdx.x; }
    else                 { A = hid; W = Wh; b = gb + 1536; C = hm; K = 512; blk = blockIdx.x - 48; }
    gemm_tile(As, Wt, A, W, b, 0, C, K, 1536, blk, 0);
}

// ------------- GRU gate combine -> dec_output -------------
__global__ __launch_bounds__(256) void k_comb(const float* __restrict__ hid, float* __restrict__ out) {
    int idx = blockIdx.x * 256 + threadIdx.x;   // 64*512 threads
    int b = idx >> 9, u = idx & 511;
    float xz = g_xm[b * 1536 + u];
    float xr = g_xm[b * 1536 + 512 + u];
    float xh = g_xm[b * 1536 + 1024 + u];
    float hz = g_hm[b * 1536 + u];
    float hr = g_hm[b * 1536 + 512 + u];
    float hh = g_hm[b * 1536 + 1024 + u];
    float z = 1.0f / (1.0f + __expf(-(xz + hz)));
    float r = 1.0f / (1.0f + __expf(-(xr + hr)));
    float hc = tanhf(xh + r * hh);
    float hp = hid[idx];
    out[idx] = z * hp + (1.0f - z) * hc;
}

// ------------- fused q / qw / dec@wd_bot GEMMs -------------
// blocks 0-15: q = dec@Ws ; 16-31: qw = dec@Ww ; 32-39: htp = dec@wd[512:,:]
__global__ __launch_bounds__(256) void k_qqw(const float* __restrict__ dec,
                                             const float* __restrict__ Ws,
                                             const float* __restrict__ Ww,
                                             const float* __restrict__ wd,
                                             float* __restrict__ q,
                                             float* __restrict__ qw,
                                             float* __restrict__ htp) {
    __shared__ __align__(16) float As[32 * 68];
    __shared__ __align__(16) float Wt[32 * 32];
    if (blockIdx.x < 16) {
        gemm_tile(As, Wt, dec, Ws, 0, 0, q, 512, 512, blockIdx.x, 0);
    } else if (blockIdx.x < 32) {
        gemm_tile(As, Wt, dec, Ww, 0, 0, qw, 512, 512, blockIdx.x - 16, 0);
    } else {
        gemm_tile(As, Wt, dec, wd + (size_t)512 * 256, 0, 0, htp, 512, 256, blockIdx.x - 32, 0);
    }
}

// ------------- sentence attention + context + p_gen (block per b) -------------
__global__ __launch_bounds__(256) void k_att(const float* __restrict__ enc_s,
                                             const float* __restrict__ emb,
                                             const float* __restrict__ wc,
                                             const float* __restrict__ wh,
                                             const float* __restrict__ wi,
                                             float* __restrict__ out) {
    int b = blockIdx.x;
    __shared__ __align__(16) float qs[512];
    __shared__ __align__(16) float dec_s[512];
    __shared__ float ctx[512];
    __shared__ float sc[32];
    __shared__ float red[8];
    int tid = threadIdx.x, wid = tid >> 5, lane = tid & 31;

    qs[tid] = g_q[b * 512 + tid];
    qs[tid + 256] = g_q[b * 512 + tid + 256];
    dec_s[tid] = out[b * 512 + tid];
    dec_s[tid + 256] = out[b * 512 + tid + 256];
    __syncthreads();

    const float4* qv4 = (const float4*)qs;
    for (int s = wid; s < NS; s += 8) {
        const float4* e = (const float4*)(enc_s + ((size_t)b * NS + s) * 512);
        float sum = 0.0f;
#pragma unroll
        for (int j = 0; j < 4; j++) {
            float4 ev = e[lane + 32 * j];
            float4 qv = qv4[lane + 32 * j];
            sum += ev.x * qv.x + ev.y * qv.y + ev.z * qv.z + ev.w * qv.w;
        }
#pragma unroll
        for (int o = 16; o; o >>= 1) sum += __shfl_xor_sync(0xffffffffu, sum, o);
        if (lane == 0) sc[s] = sum;
    }
    __syncthreads();
    if (wid == 0) {
        float v = sc[lane];
        float m = v;
#pragma unroll
        for (int o = 16; o; o >>= 1) m = fmaxf(m, __shfl_xor_sync(0xffffffffu, m, o));
        float e = __expf(v - m);
        float Z = e;
#pragma unroll
        for (int o = 16; o; o >>= 1) Z += __shfl_xor_sync(0xffffffffu, Z, o);
        float a = e / Z;
        sc[lane] = a;
        g_alpha[b * NS + lane] = a;
    }
    __syncthreads();
    for (int d = tid; d < 512; d += 256) {
        float s = 0.0f;
#pragma unroll 8
        for (int k = 0; k < NS; k++) s += sc[k] * enc_s[((size_t)b * NS + k) * 512 + d];
        ctx[d] = s;
        g_ctx[b * 512 + d] = s;
    }
    __syncthreads();
    // p_gen
    float p = ctx[tid] * wc[tid] + ctx[tid + 256] * wc[tid + 256];
    p += dec_s[tid] * wh[tid] + dec_s[tid + 256] * wh[tid + 256];
    p += emb[b * 256 + tid] * wi[tid];
#pragma unroll
    for (int o = 16; o; o >>= 1) p += __shfl_xor_sync(0xffffffffu, p, o);
    if (lane == 0) red[wid] = p;
    __syncthreads();
    if (tid == 0) {
        float t = 0.0f;
        for (int w = 0; w < 8; w++) t += red[w];
        out[PGEN_OFF + b] = 1.0f / (1.0f + __expf(-t));
    }
}

// ------------- hidden_t = tanh(ctx @ wd_top + htp) -------------
__global__ __launch_bounds__(256) void k_dec2(const float* __restrict__ wd) {
    __shared__ __align__(16) float As[32 * 68];
    __shared__ __align__(16) float Wt[32 * 32];
    gemm_tile(As, Wt, g_ctx, wd, 0, g_htp, g_ht, 512, 256, blockIdx.x, 1);
}

// ------------- FC on tensor cores (tf32 mma) + exp + row-sum partials ----------
__global__ __launch_bounds__(256) void k_fc(const float* __restrict__ fcW,
                                            const float* __restrict__ fcb,
                                            float* __restrict__ out) {
    __shared__ uint32_t Hs[64 * 36];    // stride 36: conflict-free A frags
    __shared__ __align__(16) uint32_t Wsm[32 * 136];  // stride 136
    __shared__ float bsum[64];

    int tid = threadIdx.x;
    int w = tid >> 5, lane = tid & 31;
    int gid = lane >> 2, tig = lane & 3;
    int mrow = (w & 3) * 16;
    int nloc = (w >> 2) * 64;
    int n0 = blockIdx.x * 128;

    if (tid < 64) bsum[tid] = 0.0f;

    float c[8][4];
#pragma unroll
    for (int t = 0; t < 8; t++)
#pragma unroll
        for (int j = 0; j < 4; j++) c[t][j] = 0.0f;

    for (int ks = 0; ks < 8; ks++) {
        // stage H slice [64][32]
        for (int u = tid; u < 512; u += 256) {
            int row = u >> 3, c4 = (u & 7) * 4;
            float4 v = *(const float4*)(g_ht + row * 256 + ks * 32 + c4);
            Hs[row * 36 + c4 + 0] = f2tf32(v.x);
            Hs[row * 36 + c4 + 1] = f2tf32(v.y);
            Hs[row * 36 + c4 + 2] = f2tf32(v.z);
            Hs[row * 36 + c4 + 3] = f2tf32(v.w);
        }
        // stage W slice [32][128] (uint4 stores, conflict-free)
        for (int u = tid; u < 1024; u += 256) {
            int k = u >> 5, c4 = (u & 31) * 4;
            int n = n0 + c4;
            const float* src = fcW + (size_t)(ks * 32 + k) * VV + n;
            float4 v = make_float4(0.f, 0.f, 0.f, 0.f);
            if (n + 3 < VV) v = *(const float4*)src;
            else {
                if (n     < VV) v.x = src[0];
                if (n + 1 < VV) v.y = src[1];
                if (n + 2 < VV) v.z = src[2];
            }
            uint4 t4;
            t4.x = f2tf32(v.x); t4.y = f2tf32(v.y);
            t4.z = f2tf32(v.z); t4.w = f2tf32(v.w);
            *(uint4*)&Wsm[k * 136 + c4] = t4;
        }
        __syncthreads();
#pragma unroll
        for (int k8 = 0; k8 < 4; k8++) {
            int kb = k8 * 8;
            uint32_t a0 = Hs[(mrow + gid) * 36 + kb + tig];
            uint32_t a1 = Hs[(mrow + gid + 8) * 36 + kb + tig];
            uint32_t a2 = Hs[(mrow + gid) * 36 + kb + tig + 4];
            uint32_t a3 = Hs[(mrow + gid + 8) * 36 + kb + tig + 4];
#pragma unroll
            for (int t = 0; t < 8; t++) {
                uint32_t b0 = Wsm[(kb + tig) * 136 + nloc + t * 8 + gid];
                uint32_t b1 = Wsm[(kb + tig + 4) * 136 + nloc + t * 8 + gid];
                mma_tf32(c[t][0], c[t][1], c[t][2], c[t][3], a0, a1, a2, a3, b0, b1);
            }
        }
        __syncthreads();
    }

    // epilogue: exp(logit + bias), write gen region, partial row sums
    float s0 = 0.0f, s1 = 0.0f;
    int r0 = mrow + gid, r1 = r0 + 8;
#pragma unroll
    for (int t = 0; t < 8; t++) {
        int col = n0 + nloc + t * 8 + 2 * tig;
        if (col < VV) {
            float b0v = fcb[col], b1v = fcb[col + 1];
            float e0 = __expf(c[t][0] + b0v);
            float e1 = __expf(c[t][1] + b1v);
            float e2 = __expf(c[t][2] + b0v);
            float e3 = __expf(c[t][3] + b1v);
            *(float2*)(out + GEN_OFF + (size_t)r0 * EXT + col) = make_float2(e0, e1);
            *(float2*)(out + GEN_OFF + (size_t)r1 * EXT + col) = make_float2(e2, e3);
            s0 += e0 + e1;
            s1 += e2 + e3;
        }
    }
    s0 += __shfl_xor_sync(0xffffffffu, s0, 1);
    s0 += __shfl_xor_sync(0xffffffffu, s0, 2);
    s1 += __shfl_xor_sync(0xffffffffu, s1, 1);
    s1 += __shfl_xor_sync(0xffffffffu, s1, 2);
    if (tig == 0) {
        atomicAdd(&bsum[r0], s0);
        atomicAdd(&bsum[r1], s1);
    }
    __syncthreads();
    if (tid < 64) atomicAdd(&g_rowsum[tid], bsum[tid]);
}

// ------------- normalize gen distribution -------------
__global__ __launch_bounds__(256) void k_norm(float* __restrict__ out) {
    size_t i = (size_t)blockIdx.x * blockDim.x + threadIdx.x;
    size_t stride = (size_t)gridDim.x * blockDim.x;
    size_t total = (size_t)BB * EXT;
    for (size_t t = i; t < total; t += stride) {
        int v = (int)(t % EXT);
        if (v < VV) {
            int b = (int)(t / EXT);
            out[GEN_OFF + t] *= (1.0f / g_rowsum[b]);
        }
    }
}

// ------------- word attention + scatter-add copy distribution -------------
__global__ __launch_bounds__(256) void k_watt(const float* __restrict__ enc_w,
                                              const int* __restrict__ num,
                                              float* __restrict__ out) {
    int b = blockIdx.x >> 5;
    int s = blockIdx.x & 31;
    __shared__ __align__(16) float qs[512];
    __shared__ float sc[64];
    int tid = threadIdx.x, wid = tid >> 5, lane = tid & 31;

    qs[tid] = g_qw[b * 512 + tid];
    qs[tid + 256] = g_qw[b * 512 + tid + 256];
    __syncthreads();

    const float4* qv4 = (const float4*)qs;
    for (int w = wid; w < NW; w += 8) {
        const float4* e = (const float4*)(enc_w + (((size_t)b * NS + s) * NW + w) * 512);
        float sum = 0.0f;
#pragma unroll
        for (int j = 0; j < 4; j++) {
            float4 ev = e[lane + 32 * j];
            float4 qv = qv4[lane + 32 * j];
            sum += ev.x * qv.x + ev.y * qv.y + ev.z * qv.z + ev.w * qv.w;
        }
#pragma unroll
        for (int o = 16; o; o >>= 1) sum += __shfl_xor_sync(0xffffffffu, sum, o);
        if (lane == 0) sc[w] = sum;
    }
    __syncthreads();
    if (wid == 0) {
        float v0 = (lane < NW) ? sc[lane] : -1e30f;
        float v1 = (lane + 32 < NW) ? sc[lane + 32] : -1e30f;
        float m = fmaxf(v0, v1);
#pragma unroll
        for (int o = 16; o; o >>= 1) m = fmaxf(m, __shfl_xor_sync(0xffffffffu, m, o));
        float e0 = (lane < NW) ? __expf(v0 - m) : 0.0f;
        float e1 = (lane + 32 < NW) ? __expf(v1 - m) : 0.0f;
        float Z = e0 + e1;
#pragma unroll
        for (int o = 16; o; o >>= 1) Z += __shfl_xor_sync(0xffffffffu, Z, o);
        float a = g_alpha[b * NS + s] / Z;
        if (lane < NW) sc[lane] = e0 * a;
        if (lane + 32 < NW) sc[lane + 32] = e1 * a;
    }
    __syncthreads();
    if (tid < NW) {
        int idx = num[b * (NS * NW) + s * NW + tid];
        atomicAdd(out + COPY_OFF + (size_t)b * EXT + idx, sc[tid]);
    }
}

// =================== host ===================
extern "C" void kernel_launch(void* const* d_in, const int* in_sizes, int n_in,
                              void* d_out, int out_size) {
    const float *emb = 0, *hid = 0, *enc_s = 0, *enc_w = 0;
    const float *Wx = 0, *Wh = 0, *gb = 0, *Ws = 0, *Ww = 0;
    const float *fcW = 0, *fcb = 0, *wc = 0, *wh = 0, *wd = 0, *wi = 0;
    const int* num = 0;
    int c262 = 0, c512 = 0;
    for (int i = 0; i < n_in; i++) {
        int sz = in_sizes[i];
        const float* p = (const float*)d_in[i];
        switch (sz) {
            case 16384:    emb = p; break;
            case 32768:    hid = p; break;
            case 1048576:  enc_s = p; break;
            case 52428800: enc_w = p; break;
            case 102400:   num = (const int*)d_in[i]; break;
            case 393216:   Wx = p; break;
            case 786432:   Wh = p; break;
            case 3072:     gb = p; break;
            case 12800000: fcW = p; break;
            case 50000:    fcb = p; break;
            case 256:      wi = p; break;
            case 512:      if (c512 == 0) wc = p; else wh = p; c512++; break;
            case 262144:
                if (c262 == 0) Ws = p; else if (c262 == 1) Ww = p; else wd = p;
                c262++; break;
            default: break; // batch_size scalar
        }
    }
    float* out = (float*)d_out;

    float *xm_ptr = 0, *hm_ptr = 0, *q_ptr = 0, *qw_ptr = 0, *htp_ptr = 0;
    cudaGetSymbolAddress((void**)&xm_ptr, g_xm);
    cudaGetSymbolAddress((void**)&hm_ptr, g_hm);
    cudaGetSymbolAddress((void**)&q_ptr, g_q);
    cudaGetSymbolAddress((void**)&qw_ptr, g_qw);
    cudaGetSymbolAddress((void**)&htp_ptr, g_htp);

    k_gates<<<96, 256>>>(emb, Wx, hid, Wh, gb, xm_ptr, hm_ptr);
    k_comb<<<128, 256>>>(hid, out);
    k_qqw<<<40, 256>>>(out, Ws, Ww, wd, q_ptr, qw_ptr, htp_ptr);
    k_att<<<64, 256>>>(enc_s, emb, wc, wh, wi, out);
    k_init<<<2048, 256>>>(out);
    k_dec2<<<8, 256>>>(wd);
    k_fc<<<(VV + 127) / 128, 256>>>(fcW, fcb, out);
    k_norm<<<6144, 256>>>(out);
    k_watt<<<BB * NS, 256>>>(enc_w, num, out);
}

// round 4
// speedup vs baseline: 1.5021x; 1.5021x over previous
#include <cuda_runtime.h>
#include <math.h>
#include <stdint.h>

#define BB 64
#define UU 512
#define EMBD 256
#define NS 32
#define NW 50
#define VV 50000
#define EXT 50100

// d_out layout: [dec 64*512][gen 64*50100][copy 64*50100][p_gen 64]
#define GEN_OFF   ((size_t)BB*UU)
#define COPY_OFF  (GEN_OFF + (size_t)BB*EXT)
#define PGEN_OFF  (COPY_OFF + (size_t)BB*EXT)

// ------------- scratch (no allocations allowed) -------------
__device__ float g_xm[BB*1536];
__device__ float g_hm[BB*1536];
__device__ float g_q[BB*UU];
__device__ float g_qw[BB*UU];
__device__ float g_alpha[BB*NS];
__device__ float g_htp[BB*256];   // dec @ wd_bot partial
__device__ float g_ht[BB*256];
__device__ float g_rowsum[BB];

// ------------- helpers -------------
__device__ __forceinline__ uint32_t f2tf32(float f) {
    uint32_t u;
    asm("cvt.rna.tf32.f32 %0, %1;" : "=r"(u) : "f"(f));
    return u;
}

__device__ __forceinline__ void mma_tf32(float& c0, float& c1, float& c2, float& c3,
                                         uint32_t a0, uint32_t a1, uint32_t a2, uint32_t a3,
                                         uint32_t b0, uint32_t b1) {
    asm volatile(
        "mma.sync.aligned.m16n8k8.row.col.f32.tf32.tf32.f32 "
        "{%0,%1,%2,%3}, {%4,%5,%6,%7}, {%8,%9}, {%0,%1,%2,%3};\n"
        : "+f"(c0), "+f"(c1), "+f"(c2), "+f"(c3)
        : "r"(a0), "r"(a1), "r"(a2), "r"(a3), "r"(b0), "r"(b1));
}

// ------------- small GEMM tile: C[64, 32-col tile] = A[64,K] @ W[K,N] -------------
__device__ __forceinline__ void gemm_tile(float* As, float* Wt,
                                          const float* __restrict__ A,
                                          const float* __restrict__ W,
                                          const float* __restrict__ bias,
                                          float* __restrict__ C,
                                          int K, int N, int blk) {
    int tid = threadIdx.x;
    int c  = tid & 31;
    int rg = tid >> 5;            // 8 row groups of 8 rows
    int n0 = blk * 32;
    int n  = n0 + c;

    float acc[8];
#pragma unroll
    for (int r = 0; r < 8; r++) acc[r] = 0.0f;

    for (int k0 = 0; k0 < K; k0 += 32) {
        for (int i = tid; i < 2048; i += 256) {
            int k = i & 31, b = i >> 5;
            As[k * 68 + b] = A[(size_t)b * K + k0 + k];
        }
        for (int i = tid; i < 1024; i += 256) {
            int kk = i >> 5, c2 = i & 31;
            Wt[kk * 32 + c2] = W[(size_t)(k0 + kk) * N + n0 + c2];
        }
        __syncthreads();
#pragma unroll 8
        for (int kk = 0; kk < 32; kk++) {
            float w = Wt[kk * 32 + c];
            float4 a0 = *(const float4*)&As[kk * 68 + rg * 8];
            float4 a1 = *(const float4*)&As[kk * 68 + rg * 8 + 4];
            acc[0] += a0.x * w; acc[1] += a0.y * w;
            acc[2] += a0.z * w; acc[3] += a0.w * w;
            acc[4] += a1.x * w; acc[5] += a1.y * w;
            acc[6] += a1.z * w; acc[7] += a1.w * w;
        }
        __syncthreads();
    }
    float bv = bias ? bias[n] : 0.0f;
#pragma unroll
    for (int r = 0; r < 8; r++) {
        int row = rg * 8 + r;
        C[(size_t)row * N + n] = acc[r] + bv;
    }
}

// ------------- fused GRU gate GEMMs: blocks 0-47 xm, 48-95 hm -------------
__global__ __launch_bounds__(256) void k_gates(const float* __restrict__ emb,
                                               const float* __restrict__ Wx,
                                               const float* __restrict__ hid,
                                               const float* __restrict__ Wh,
                                               const float* __restrict__ gb,
                                               float* __restrict__ xm,
                                               float* __restrict__ hm) {
    __shared__ __align__(16) float As[32 * 68];
    __shared__ __align__(16) float Wt[32 * 32];
    const float* A; const float* W; const float* b; float* C; int K; int blk;
    if (blockIdx.x < 48) { A = emb; W = Wx; b = gb;        C = xm; K = 256; blk = blockIdx.x; }
    else                 { A = hid; W = Wh; b = gb + 1536; C = hm; K = 512; blk = blockIdx.x - 48; }
    gemm_tile(As, Wt, A, W, b, C, K, 1536, blk);
}

// ------------- GRU gate combine -> dec_output -------------
__global__ __launch_bounds__(256) void k_comb(const float* __restrict__ hid, float* __restrict__ out) {
    int idx = blockIdx.x * 256 + threadIdx.x;   // 64*512 threads
    int b = idx >> 9, u = idx & 511;
    float xz = g_xm[b * 1536 + u];
    float xr = g_xm[b * 1536 + 512 + u];
    float xh = g_xm[b * 1536 + 1024 + u];
    float hz = g_hm[b * 1536 + u];
    float hr = g_hm[b * 1536 + 512 + u];
    float hh = g_hm[b * 1536 + 1024 + u];
    float z = 1.0f / (1.0f + __expf(-(xz + hz)));
    float r = 1.0f / (1.0f + __expf(-(xr + hr)));
    float hc = tanhf(xh + r * hh);
    float hp = hid[idx];
    out[idx] = z * hp + (1.0f - z) * hc;
}

// ------------- fused q / qw / htp GEMMs + output-region init -------------
// blocks 0-15: q ; 16-31: qw ; 32-39: htp = dec@wd[512:,:] ; 40+: init zeroing
__global__ __launch_bounds__(256) void k_qqwinit(const float* __restrict__ dec,
                                                 const float* __restrict__ Ws,
                                                 const float* __restrict__ Ww,
                                                 const float* __restrict__ wd,
                                                 float* __restrict__ q,
                                                 float* __restrict__ qw,
                                                 float* __restrict__ htp,
                                                 float* __restrict__ out) {
    __shared__ __align__(16) float As[32 * 68];
    __shared__ __align__(16) float Wt[32 * 32];
    if (blockIdx.x < 16) {
        gemm_tile(As, Wt, dec, Ws, 0, q, 512, 512, blockIdx.x);
    } else if (blockIdx.x < 32) {
        gemm_tile(As, Wt, dec, Ww, 0, qw, 512, 512, blockIdx.x - 16);
    } else if (blockIdx.x < 40) {
        gemm_tile(As, Wt, dec, wd + (size_t)512 * 256, 0, htp, 512, 256, blockIdx.x - 32);
    } else {
        size_t i = (size_t)(blockIdx.x - 40) * 256 + threadIdx.x;
        size_t total = (size_t)BB * EXT;
        size_t stride = (size_t)2048 * 256;
        for (size_t t = i; t < total; t += stride) {
            out[COPY_OFF + t] = 0.0f;
            int v = (int)(t % EXT);
            if (v >= VV) out[GEN_OFF + t] = 0.0f;
        }
        if (i < BB) g_rowsum[i] = 0.0f;
    }
}

// ------------- sentence attention + context + p_gen + hidden_t (block per b) ------
__global__ __launch_bounds__(256) void k_att(const float* __restrict__ enc_s,
                                             const float* __restrict__ emb,
                                             const float* __restrict__ wc,
                                             const float* __restrict__ wh,
                                             const float* __restrict__ wi,
                                             const float* __restrict__ wd,
                                             float* __restrict__ out) {
    int b = blockIdx.x;
    __shared__ __align__(16) float qs[512];
    __shared__ __align__(16) float dec_s[512];
    __shared__ __align__(16) float ctx[512];
    __shared__ __align__(16) float wdsm[32 * 256];
    __shared__ float sc[32];
    __shared__ float red[8];
    int tid = threadIdx.x, wid = tid >> 5, lane = tid & 31;

    qs[tid] = g_q[b * 512 + tid];
    qs[tid + 256] = g_q[b * 512 + tid + 256];
    dec_s[tid] = out[b * 512 + tid];
    dec_s[tid + 256] = out[b * 512 + tid + 256];
    __syncthreads();

    const float4* qv4 = (const float4*)qs;
    for (int s = wid; s < NS; s += 8) {
        const float4* e = (const float4*)(enc_s + ((size_t)b * NS + s) * 512);
        float sum = 0.0f;
#pragma unroll
        for (int j = 0; j < 4; j++) {
            float4 ev = e[lane + 32 * j];
            float4 qv = qv4[lane + 32 * j];
            sum += ev.x * qv.x + ev.y * qv.y + ev.z * qv.z + ev.w * qv.w;
        }
#pragma unroll
        for (int o = 16; o; o >>= 1) sum += __shfl_xor_sync(0xffffffffu, sum, o);
        if (lane == 0) sc[s] = sum;
    }
    __syncthreads();
    if (wid == 0) {
        float v = sc[lane];
        float m = v;
#pragma unroll
        for (int o = 16; o; o >>= 1) m = fmaxf(m, __shfl_xor_sync(0xffffffffu, m, o));
        float e = __expf(v - m);
        float Z = e;
#pragma unroll
        for (int o = 16; o; o >>= 1) Z += __shfl_xor_sync(0xffffffffu, Z, o);
        float a = e / Z;
        sc[lane] = a;
        g_alpha[b * NS + lane] = a;
    }
    __syncthreads();
    for (int d = tid; d < 512; d += 256) {
        float s = 0.0f;
#pragma unroll 8
        for (int k = 0; k < NS; k++) s += sc[k] * enc_s[((size_t)b * NS + k) * 512 + d];
        ctx[d] = s;
    }
    __syncthreads();
    // p_gen
    float p = ctx[tid] * wc[tid] + ctx[tid + 256] * wc[tid + 256];
    p += dec_s[tid] * wh[tid] + dec_s[tid + 256] * wh[tid + 256];
    p += emb[b * 256 + tid] * wi[tid];
#pragma unroll
    for (int o = 16; o; o >>= 1) p += __shfl_xor_sync(0xffffffffu, p, o);
    if (lane == 0) red[wid] = p;
    __syncthreads();
    if (tid == 0) {
        float t = 0.0f;
        for (int w = 0; w < 8; w++) t += red[w];
        out[PGEN_OFF + b] = 1.0f / (1.0f + __expf(-t));
    }
    // hidden_t: ht[b][tid] = tanh( sum_k ctx[k]*wd[k][tid] + htp[b][tid] )
    float acc = g_htp[b * 256 + tid];
    for (int k0 = 0; k0 < 512; k0 += 32) {
        __syncthreads();
#pragma unroll
        for (int t = 0; t < 8; t++) {
            int e = (tid + t * 256) * 4;          // element index in 32x256 tile
            int kk = e >> 8, col = e & 255;
            *(float4*)&wdsm[kk * 256 + col] =
                *(const float4*)(wd + (size_t)(k0 + kk) * 256 + col);
        }
        __syncthreads();
#pragma unroll 8
        for (int kk = 0; kk < 32; kk++)
            acc += ctx[k0 + kk] * wdsm[kk * 256 + tid];
    }
    g_ht[b * 256 + tid] = tanhf(acc);
}

// ------------- FC on tensor cores (tf32 mma) + exp + row-sum partials ----------
__global__ __launch_bounds__(256) void k_fc(const float* __restrict__ fcW,
                                            const float* __restrict__ fcb,
                                            float* __restrict__ out) {
    __shared__ uint32_t Hs[64 * 36];    // stride 36: conflict-free A frags
    __shared__ __align__(16) uint32_t Wsm[32 * 136];  // stride 136
    __shared__ float bsum[64];

    int tid = threadIdx.x;
    int w = tid >> 5, lane = tid & 31;
    int gid = lane >> 2, tig = lane & 3;
    int mrow = (w & 3) * 16;
    int nloc = (w >> 2) * 64;
    int n0 = blockIdx.x * 128;

    if (tid < 64) bsum[tid] = 0.0f;

    float c[8][4];
#pragma unroll
    for (int t = 0; t < 8; t++)
#pragma unroll
        for (int j = 0; j < 4; j++) c[t][j] = 0.0f;

    for (int ks = 0; ks < 8; ks++) {
        // stage H slice [64][32]
        for (int u = tid; u < 512; u += 256) {
            int row = u >> 3, c4 = (u & 7) * 4;
            float4 v = *(const float4*)(g_ht + row * 256 + ks * 32 + c4);
            Hs[row * 36 + c4 + 0] = f2tf32(v.x);
            Hs[row * 36 + c4 + 1] = f2tf32(v.y);
            Hs[row * 36 + c4 + 2] = f2tf32(v.z);
            Hs[row * 36 + c4 + 3] = f2tf32(v.w);
        }
        // stage W slice [32][128]
        for (int u = tid; u < 1024; u += 256) {
            int k = u >> 5, c4 = (u & 31) * 4;
            int n = n0 + c4;
            const float* src = fcW + (size_t)(ks * 32 + k) * VV + n;
            float4 v = make_float4(0.f, 0.f, 0.f, 0.f);
            if (n + 3 < VV) v = *(const float4*)src;
            else {
                if (n     < VV) v.x = src[0];
                if (n + 1 < VV) v.y = src[1];
                if (n + 2 < VV) v.z = src[2];
            }
            uint4 t4;
            t4.x = f2tf32(v.x); t4.y = f2tf32(v.y);
            t4.z = f2tf32(v.z); t4.w = f2tf32(v.w);
            *(uint4*)&Wsm[k * 136 + c4] = t4;
        }
        __syncthreads();
#pragma unroll
        for (int k8 = 0; k8 < 4; k8++) {
            int kb = k8 * 8;
            uint32_t a0 = Hs[(mrow + gid) * 36 + kb + tig];
            uint32_t a1 = Hs[(mrow + gid + 8) * 36 + kb + tig];
            uint32_t a2 = Hs[(mrow + gid) * 36 + kb + tig + 4];
            uint32_t a3 = Hs[(mrow + gid + 8) * 36 + kb + tig + 4];
#pragma unroll
            for (int t = 0; t < 8; t++) {
                uint32_t b0 = Wsm[(kb + tig) * 136 + nloc + t * 8 + gid];
                uint32_t b1 = Wsm[(kb + tig + 4) * 136 + nloc + t * 8 + gid];
                mma_tf32(c[t][0], c[t][1], c[t][2], c[t][3], a0, a1, a2, a3, b0, b1);
            }
        }
        __syncthreads();
    }

    // epilogue: exp(logit + bias), write gen region, partial row sums
    float s0 = 0.0f, s1 = 0.0f;
    int r0 = mrow + gid, r1 = r0 + 8;
#pragma unroll
    for (int t = 0; t < 8; t++) {
        int col = n0 + nloc + t * 8 + 2 * tig;
        if (col < VV) {
            float b0v = fcb[col], b1v = fcb[col + 1];
            float e0 = __expf(c[t][0] + b0v);
            float e1 = __expf(c[t][1] + b1v);
            float e2 = __expf(c[t][2] + b0v);
            float e3 = __expf(c[t][3] + b1v);
            *(float2*)(out + GEN_OFF + (size_t)r0 * EXT + col) = make_float2(e0, e1);
            *(float2*)(out + GEN_OFF + (size_t)r1 * EXT + col) = make_float2(e2, e3);
            s0 += e0 + e1;
            s1 += e2 + e3;
        }
    }
    s0 += __shfl_xor_sync(0xffffffffu, s0, 1);
    s0 += __shfl_xor_sync(0xffffffffu, s0, 2);
    s1 += __shfl_xor_sync(0xffffffffu, s1, 1);
    s1 += __shfl_xor_sync(0xffffffffu, s1, 2);
    if (tig == 0) {
        atomicAdd(&bsum[r0], s0);
        atomicAdd(&bsum[r1], s1);
    }
    __syncthreads();
    if (tid < 64) atomicAdd(&g_rowsum[tid], bsum[tid]);
}

// ------------- word attention + copy scatter (blocks 0-2047) + gen normalize -----
__global__ __launch_bounds__(256) void k_wattnorm(const float* __restrict__ enc_w,
                                                  const int* __restrict__ num,
                                                  float* __restrict__ out) {
    if (blockIdx.x >= BB * NS) {
        // normalize gen distribution
        size_t i = (size_t)(blockIdx.x - BB * NS) * 256 + threadIdx.x;
        size_t stride = (size_t)512 * 256;
        size_t total = (size_t)BB * EXT;
        for (size_t t = i; t < total; t += stride) {
            int v = (int)(t % EXT);
            if (v < VV) {
                int b = (int)(t / EXT);
                out[GEN_OFF + t] *= (1.0f / g_rowsum[b]);
            }
        }
        return;
    }
    int b = blockIdx.x >> 5;
    int s = blockIdx.x & 31;
    __shared__ __align__(16) float qs[512];
    __shared__ float sc[64];
    int tid = threadIdx.x, wid = tid >> 5, lane = tid & 31;

    qs[tid] = g_qw[b * 512 + tid];
    qs[tid + 256] = g_qw[b * 512 + tid + 256];
    __syncthreads();

    const float4* qv4 = (const float4*)qs;
    for (int w = wid; w < NW; w += 8) {
        const float4* e = (const float4*)(enc_w + (((size_t)b * NS + s) * NW + w) * 512);
        float sum = 0.0f;
#pragma unroll
        for (int j = 0; j < 4; j++) {
            float4 ev = e[lane + 32 * j];
            float4 qv = qv4[lane + 32 * j];
            sum += ev.x * qv.x + ev.y * qv.y + ev.z * qv.z + ev.w * qv.w;
        }
#pragma unroll
        for (int o = 16; o; o >>= 1) sum += __shfl_xor_sync(0xffffffffu, sum, o);
        if (lane == 0) sc[w] = sum;
    }
    __syncthreads();
    if (wid == 0) {
        float v0 = (lane < NW) ? sc[lane] : -1e30f;
        float v1 = (lane + 32 < NW) ? sc[lane + 32] : -1e30f;
        float m = fmaxf(v0, v1);
#pragma unroll
        for (int o = 16; o; o >>= 1) m = fmaxf(m, __shfl_xor_sync(0xffffffffu, m, o));
        float e0 = (lane < NW) ? __expf(v0 - m) : 0.0f;
        float e1 = (lane + 32 < NW) ? __expf(v1 - m) : 0.0f;
        float Z = e0 + e1;
#pragma unroll
        for (int o = 16; o; o >>= 1) Z += __shfl_xor_sync(0xffffffffu, Z, o);
        float a = g_alpha[b * NS + s] / Z;
        if (lane < NW) sc[lane] = e0 * a;
        if (lane + 32 < NW) sc[lane + 32] = e1 * a;
    }
    __syncthreads();
    if (tid < NW) {
        int idx = num[b * (NS * NW) + s * NW + tid];
        atomicAdd(out + COPY_OFF + (size_t)b * EXT + idx, sc[tid]);
    }
}

// =================== host ===================
extern "C" void kernel_launch(void* const* d_in, const int* in_sizes, int n_in,
                              void* d_out, int out_size) {
    const float *emb = 0, *hid = 0, *enc_s = 0, *enc_w = 0;
    const float *Wx = 0, *Wh = 0, *gb = 0, *Ws = 0, *Ww = 0;
    const float *fcW = 0, *fcb = 0, *wc = 0, *wh = 0, *wd = 0, *wi = 0;
    const int* num = 0;
    int c262 = 0, c512 = 0;
    for (int i = 0; i < n_in; i++) {
        int sz = in_sizes[i];
        const float* p = (const float*)d_in[i];
        switch (sz) {
            case 16384:    emb = p; break;
            case 32768:    hid = p; break;
            case 1048576:  enc_s = p; break;
            case 52428800: enc_w = p; break;
            case 102400:   num = (const int*)d_in[i]; break;
            case 393216:   Wx = p; break;
            case 786432:   Wh = p; break;
            case 3072:     gb = p; break;
            case 12800000: fcW = p; break;
            case 50000:    fcb = p; break;
            case 256:      wi = p; break;
            case 512:      if (c512 == 0) wc = p; else wh = p; c512++; break;
            case 262144:
                if (c262 == 0) Ws = p; else if (c262 == 1) Ww = p; else wd = p;
                c262++; break;
            default: break; // batch_size scalar
        }
    }
    float* out = (float*)d_out;

    float *xm_ptr = 0, *hm_ptr = 0, *q_ptr = 0, *qw_ptr = 0, *htp_ptr = 0;
    cudaGetSymbolAddress((void**)&xm_ptr, g_xm);
    cudaGetSymbolAddress((void**)&hm_ptr, g_hm);
    cudaGetSymbolAddress((void**)&q_ptr, g_q);
    cudaGetSymbolAddress((void**)&qw_ptr, g_qw);
    cudaGetSymbolAddress((void**)&htp_ptr, g_htp);

    k_gates<<<96, 256>>>(emb, Wx, hid, Wh, gb, xm_ptr, hm_ptr);
    k_comb<<<128, 256>>>(hid, out);
    k_qqwinit<<<2088, 256>>>(out, Ws, Ww, wd, q_ptr, qw_ptr, htp_ptr, out);
    k_att<<<64, 256>>>(enc_s, emb, wc, wh, wi, wd, out);
    k_fc<<<(VV + 127) / 128, 256>>>(fcW, fcb, out);
    k_wattnorm<<<BB * NS + 512, 256>>>(enc_w, num, out);
}

// round 7
// speedup vs baseline: 1.9428x; 1.2934x over previous
#include <cuda_runtime.h>
#include <math.h>
#include <stdint.h>

#define BB 64
#define UU 512
#define EMBD 256
#define NS 32
#define NW 50
#define VV 50000
#define EXT 50100

#define GEN_OFF   ((size_t)BB*UU)
#define COPY_OFF  (GEN_OFF + (size_t)BB*EXT)
#define PGEN_OFF  (COPY_OFF + (size_t)BB*EXT)

#define SMALL_GRID 128

// ------------- scratch -------------
__device__ float g_xm[BB*1536];
__device__ float g_hm[BB*1536];
__device__ float g_q[BB*UU];
__device__ float g_qw[BB*UU];
__device__ float g_alpha[BB*NS];
__device__ float g_ctx[BB*UU];
__device__ float g_ht[BB*256];       // pre-tanh: htp + ctx@wd_top (atomics)
__device__ float g_rowsum[BB];
__device__ float g_wsc[BB*NS*NW];    // raw word scores
__device__ unsigned long long g_bar; // monotonic ticket barrier

// ------------- helpers -------------
__device__ __forceinline__ uint32_t f2tf32(float f) {
    uint32_t u;
    asm("cvt.rna.tf32.f32 %0, %1;" : "=r"(u) : "f"(f));
    return u;
}

__device__ __forceinline__ void mma_tf32(float& c0, float& c1, float& c2, float& c3,
                                         uint32_t a0, uint32_t a1, uint32_t a2, uint32_t a3,
                                         uint32_t b0, uint32_t b1) {
    asm volatile(
        "mma.sync.aligned.m16n8k8.row.col.f32.tf32.tf32.f32 "
        "{%0,%1,%2,%3}, {%4,%5,%6,%7}, {%8,%9}, {%0,%1,%2,%3};\n"
        : "+f"(c0), "+f"(c1), "+f"(c2), "+f"(c3)
        : "r"(a0), "r"(a1), "r"(a2), "r"(a3), "r"(b0), "r"(b1));
}

// grid-wide barrier: monotonic ticket counter, deterministic across graph replays
__device__ __forceinline__ void grid_bar() {
    __syncthreads();
    if (threadIdx.x == 0) {
        __threadfence();
        unsigned long long ticket = atomicAdd(&g_bar, 1ULL);
        unsigned long long target = (ticket / SMALL_GRID + 1ULL) * SMALL_GRID;
        while (*(volatile unsigned long long*)&g_bar < target) { }
        __threadfence();
    }
    __syncthreads();
}

// ------------- small GEMM tile: C[64, 32-col tile] = A[64,K] @ W[K,N] -------------
__device__ __forceinline__ void gemm_tile(float* As, float* Wt,
                                          const float* __restrict__ A, int lda,
                                          const float* __restrict__ W, int ldw,
                                          const float* __restrict__ bias,
                                          float* __restrict__ C, int ldc,
                                          int K, int blk, int atomic_out) {
    int tid = threadIdx.x;
    int c  = tid & 31;
    int rg = tid >> 5;
    int n0 = blk * 32;
    int n  = n0 + c;

    float acc[8];
#pragma unroll
    for (int r = 0; r < 8; r++) acc[r] = 0.0f;

    for (int k0 = 0; k0 < K; k0 += 32) {
        for (int i = tid; i < 2048; i += 256) {
            int k = i & 31, b = i >> 5;
            As[k * 68 + b] = A[(size_t)b * lda + k0 + k];
        }
        for (int i = tid; i < 1024; i += 256) {
            int kk = i >> 5, c2 = i & 31;
            Wt[kk * 32 + c2] = W[(size_t)(k0 + kk) * ldw + n0 + c2];
        }
        __syncthreads();
#pragma unroll 8
        for (int kk = 0; kk < 32; kk++) {
            float w = Wt[kk * 32 + c];
            float4 a0 = *(const float4*)&As[kk * 68 + rg * 8];
            float4 a1 = *(const float4*)&As[kk * 68 + rg * 8 + 4];
            acc[0] += a0.x * w; acc[1] += a0.y * w;
            acc[2] += a0.z * w; acc[3] += a0.w * w;
            acc[4] += a1.x * w; acc[5] += a1.y * w;
            acc[6] += a1.z * w; acc[7] += a1.w * w;
        }
        __syncthreads();
    }
#pragma unroll
    for (int r = 0; r < 8; r++) {
        int row = rg * 8 + r;
        if (atomic_out) {
            atomicAdd(&C[(size_t)row * ldc + n], acc[r]);
        } else {
            float bv = bias ? bias[n] : 0.0f;
            C[(size_t)row * ldc + n] = acc[r] + bv;
        }
    }
}

// ======= persistent small-chain kernel: gates -> comb -> q/qw/htp -> att -> dec2 ====
__global__ __launch_bounds__(256) void k_small(const float* __restrict__ emb,
                                               const float* __restrict__ hid,
                                               const float* __restrict__ enc_s,
                                               const float* __restrict__ Wx,
                                               const float* __restrict__ Wh,
                                               const float* __restrict__ gb,
                                               const float* __restrict__ Ws,
                                               const float* __restrict__ Ww,
                                               const float* __restrict__ wd,
                                               const float* __restrict__ wc,
                                               const float* __restrict__ wh,
                                               const float* __restrict__ wi,
                                               float* __restrict__ out) {
    __shared__ __align__(16) float sm[3200];   // union across phases
    float* As = sm;            // 2176 floats
    float* Wt = sm + 2176;     // 1024 floats
    int bid = blockIdx.x, tid = threadIdx.x;
    int wid = tid >> 5, lane = tid & 31;

    // ---- phase 1: GRU gate GEMMs + zero copy/pad/rowsum ----
    if (bid < 48) {
        gemm_tile(As, Wt, emb, 256, Wx, 1536, gb, g_xm, 1536, 256, bid, 0);
    } else if (bid < 96) {
        gemm_tile(As, Wt, hid, 512, Wh, 1536, gb + 1536, g_hm, 1536, 512, bid - 48, 0);
    } else {
        float4 z4 = make_float4(0.f, 0.f, 0.f, 0.f);
        size_t total4 = (size_t)BB * EXT / 4;
        for (size_t t = (size_t)(bid - 96) * 256 + tid; t < total4; t += 32 * 256)
            *(float4*)(out + COPY_OFF + t * 4) = z4;
        for (int t = (bid - 96) * 256 + tid; t < BB * 100; t += 32 * 256) {
            int b = t / 100, v = t % 100;
            out[GEN_OFF + (size_t)b * EXT + VV + v] = 0.0f;
        }
        if (bid == 96 && tid < BB) g_rowsum[tid] = 0.0f;
    }
    grid_bar();

    // ---- phase 2: GRU combine -> dec (in out[0:64*512]) ----
    {
        int idx = bid * 256 + tid;   // exactly 32768 threads
        int b = idx >> 9, u = idx & 511;
        float xz = g_xm[b * 1536 + u];
        float xr = g_xm[b * 1536 + 512 + u];
        float xh = g_xm[b * 1536 + 1024 + u];
        float hz = g_hm[b * 1536 + u];
        float hr = g_hm[b * 1536 + 512 + u];
        float hh = g_hm[b * 1536 + 1024 + u];
        float z = 1.0f / (1.0f + __expf(-(xz + hz)));
        float r = 1.0f / (1.0f + __expf(-(xr + hr)));
        float hc = tanhf(xh + r * hh);
        out[idx] = z * hid[idx] + (1.0f - z) * hc;
    }
    grid_bar();

    // ---- phase 3: q, qw, ht_partial = dec @ wd_bot ----
    if (bid < 16) {
        gemm_tile(As, Wt, out, 512, Ws, 512, 0, g_q, 512, 512, bid, 0);
    } else if (bid < 32) {
        gemm_tile(As, Wt, out, 512, Ww, 512, 0, g_qw, 512, 512, bid - 16, 0);
    } else if (bid < 40) {
        gemm_tile(As, Wt, out, 512, wd + (size_t)512 * 256, 256, 0, g_ht, 256, 512, bid - 32, 0);
    }
    grid_bar();

    // ---- phase 4: sentence attention + context + p_gen (blocks 0-63) ----
    if (bid < 64) {
        int b = bid;
        float* qs    = sm;
        float* dec_s = sm + 512;
        float* ctxS  = sm + 1024;
        float* sc    = sm + 1536;
        float* red   = sm + 1576;

        qs[tid] = g_q[b * 512 + tid];
        qs[tid + 256] = g_q[b * 512 + tid + 256];
        dec_s[tid] = out[b * 512 + tid];
        dec_s[tid + 256] = out[b * 512 + tid + 256];
        __syncthreads();

        const float4* qv4 = (const float4*)qs;
        for (int s = wid; s < NS; s += 8) {
            const float4* e = (const float4*)(enc_s + ((size_t)b * NS + s) * 512);
            float sum = 0.0f;
#pragma unroll
            for (int j = 0; j < 4; j++) {
                float4 ev = e[lane + 32 * j];
                float4 qv = qv4[lane + 32 * j];
                sum += ev.x * qv.x + ev.y * qv.y + ev.z * qv.z + ev.w * qv.w;
            }
#pragma unroll
            for (int o = 16; o; o >>= 1) sum += __shfl_xor_sync(0xffffffffu, sum, o);
            if (lane == 0) sc[s] = sum;
        }
        __syncthreads();
        if (wid == 0) {
            float v = sc[lane];
            float m = v;
#pragma unroll
            for (int o = 16; o; o >>= 1) m = fmaxf(m, __shfl_xor_sync(0xffffffffu, m, o));
            float e = __expf(v - m);
            float Z = e;
#pragma unroll
            for (int o = 16; o; o >>= 1) Z += __shfl_xor_sync(0xffffffffu, Z, o);
            float a = e / Z;
            sc[lane] = a;
            g_alpha[b * NS + lane] = a;
        }
        __syncthreads();
        for (int d = tid; d < 512; d += 256) {
            float s = 0.0f;
#pragma unroll 8
            for (int k = 0; k < NS; k++) s += sc[k] * enc_s[((size_t)b * NS + k) * 512 + d];
            ctxS[d] = s;
            g_ctx[b * 512 + d] = s;
        }
        __syncthreads();
        float p = ctxS[tid] * wc[tid] + ctxS[tid + 256] * wc[tid + 256];
        p += dec_s[tid] * wh[tid] + dec_s[tid + 256] * wh[tid + 256];
        p += emb[b * 256 + tid] * wi[tid];
#pragma unroll
        for (int o = 16; o; o >>= 1) p += __shfl_xor_sync(0xffffffffu, p, o);
        if (lane == 0) red[wid] = p;
        __syncthreads();
        if (tid == 0) {
            float t = 0.0f;
            for (int w = 0; w < 8; w++) t += red[w];
            out[PGEN_OFF + b] = 1.0f / (1.0f + __expf(-t));
        }
        __syncthreads();
    }
    grid_bar();

    // ---- phase 5: g_ht += ctx @ wd_top  (8 N-tiles x 8 K-chunks of 64) ----
    if (bid < 64) {
        int nt = bid & 7, kc = bid >> 3;
        gemm_tile(As, Wt, g_ctx + kc * 64, 512, wd + (size_t)(kc * 64) * 256, 256,
                  0, g_ht, 256, 64, nt, 1);
    }
    // tanh applied in k_fc staging
}

// ------------- word scores: g_wsc[b,s,w] = qw[b] . enc_w[b,s,w,:] -------------
__global__ __launch_bounds__(256) void k_wscore(const float* __restrict__ enc_w) {
    int b = blockIdx.x >> 5;
    int s = blockIdx.x & 31;
    __shared__ __align__(16) float qs[512];
    int tid = threadIdx.x, wid = tid >> 5, lane = tid & 31;

    qs[tid] = g_qw[b * 512 + tid];
    qs[tid + 256] = g_qw[b * 512 + tid + 256];
    __syncthreads();

    const float4* qv4 = (const float4*)qs;
    const float4* ebase = (const float4*)(enc_w + ((size_t)b * NS + s) * NW * 512);
    float* scout = g_wsc + ((size_t)b * NS + s) * NW;

    // pairs (w, w+8): MLP 8
#pragma unroll
    for (int w0 = 0; w0 < 48; w0 += 16) {
        int wa = w0 + wid, wb = wa + 8;
        const float4* ea = ebase + (size_t)wa * 128;
        const float4* eb = ebase + (size_t)wb * 128;
        float sa = 0.0f, sb = 0.0f;
#pragma unroll
        for (int j = 0; j < 4; j++) {
            float4 qv = qv4[lane + 32 * j];
            float4 va = __ldcs(ea + lane + 32 * j);
            float4 vb = __ldcs(eb + lane + 32 * j);
            sa += va.x * qv.x + va.y * qv.y + va.z * qv.z + va.w * qv.w;
            sb += vb.x * qv.x + vb.y * qv.y + vb.z * qv.z + vb.w * qv.w;
        }
#pragma unroll
        for (int o = 16; o; o >>= 1) {
            sa += __shfl_xor_sync(0xffffffffu, sa, o);
            sb += __shfl_xor_sync(0xffffffffu, sb, o);
        }
        if (lane == 0) { scout[wa] = sa; scout[wb] = sb; }
    }
    if (wid < 2) {     // words 48, 49
        int wa = 48 + wid;
        const float4* ea = ebase + (size_t)wa * 128;
        float sa = 0.0f;
#pragma unroll
        for (int j = 0; j < 4; j++) {
            float4 qv = qv4[lane + 32 * j];
            float4 va = __ldcs(ea + lane + 32 * j);
            sa += va.x * qv.x + va.y * qv.y + va.z * qv.z + va.w * qv.w;
        }
#pragma unroll
        for (int o = 16; o; o >>= 1) sa += __shfl_xor_sync(0xffffffffu, sa, o);
        if (lane == 0) scout[wa] = sa;
    }
}

// ------------- FC on tensor cores (tf32) + exp + row-sum partials ----------
__global__ __launch_bounds__(256) void k_fc(const float* __restrict__ fcW,
                                            const float* __restrict__ fcb,
                                            float* __restrict__ out) {
    __shared__ uint32_t Hs[64 * 36];
    __shared__ __align__(16) uint32_t Wsm[32 * 136];
    __shared__ float bsum[64];

    int tid = threadIdx.x;
    int w = tid >> 5, lane = tid & 31;
    int gid = lane >> 2, tig = lane & 3;
    int mrow = (w & 3) * 16;
    int nloc = (w >> 2) * 64;
    int n0 = blockIdx.x * 128;

    if (tid < 64) bsum[tid] = 0.0f;

    float c[8][4];
#pragma unroll
    for (int t = 0; t < 8; t++)
#pragma unroll
        for (int j = 0; j < 4; j++) c[t][j] = 0.0f;

    for (int ks = 0; ks < 8; ks++) {
        for (int u = tid; u < 512; u += 256) {
            int row = u >> 3, c4 = (u & 7) * 4;
            float4 v = *(const float4*)(g_ht + row * 256 + ks * 32 + c4);
            Hs[row * 36 + c4 + 0] = f2tf32(tanhf(v.x));
            Hs[row * 36 + c4 + 1] = f2tf32(tanhf(v.y));
            Hs[row * 36 + c4 + 2] = f2tf32(tanhf(v.z));
            Hs[row * 36 + c4 + 3] = f2tf32(tanhf(v.w));
        }
        for (int u = tid; u < 1024; u += 256) {
            int k = u >> 5, c4 = (u & 31) * 4;
            int n = n0 + c4;
            const float* src = fcW + (size_t)(ks * 32 + k) * VV + n;
            float4 v = make_float4(0.f, 0.f, 0.f, 0.f);
            if (n + 3 < VV) v = *(const float4*)src;
            else {
                if (n     < VV) v.x = src[0];
                if (n + 1 < VV) v.y = src[1];
                if (n + 2 < VV) v.z = src[2];
            }
            uint4 t4;
            t4.x = f2tf32(v.x); t4.y = f2tf32(v.y);
            t4.z = f2tf32(v.z); t4.w = f2tf32(v.w);
            *(uint4*)&Wsm[k * 136 + c4] = t4;
        }
        __syncthreads();
#pragma unroll
        for (int k8 = 0; k8 < 4; k8++) {
            int kb = k8 * 8;
            uint32_t a0 = Hs[(mrow + gid) * 36 + kb + tig];
            uint32_t a1 = Hs[(mrow + gid + 8) * 36 + kb + tig];
            uint32_t a2 = Hs[(mrow + gid) * 36 + kb + tig + 4];
            uint32_t a3 = Hs[(mrow + gid + 8) * 36 + kb + tig + 4];
#pragma unroll
            for (int t = 0; t < 8; t++) {
                uint32_t b0 = Wsm[(kb + tig) * 136 + nloc + t * 8 + gid];
                uint32_t b1 = Wsm[(kb + tig + 4) * 136 + nloc + t * 8 + gid];
                mma_tf32(c[t][0], c[t][1], c[t][2], c[t][3], a0, a1, a2, a3, b0, b1);
            }
        }
        __syncthreads();
    }

    float s0 = 0.0f, s1 = 0.0f;
    int r0 = mrow + gid, r1 = r0 + 8;
#pragma unroll
    for (int t = 0; t < 8; t++) {
        int col = n0 + nloc + t * 8 + 2 * tig;
        if (col < VV) {
            float b0v = fcb[col], b1v = fcb[col + 1];
            float e0 = __expf(c[t][0] + b0v);
            float e1 = __expf(c[t][1] + b1v);
            float e2 = __expf(c[t][2] + b0v);
            float e3 = __expf(c[t][3] + b1v);
            *(float2*)(out + GEN_OFF + (size_t)r0 * EXT + col) = make_float2(e0, e1);
            *(float2*)(out + GEN_OFF + (size_t)r1 * EXT + col) = make_float2(e2, e3);
            s0 += e0 + e1;
            s1 += e2 + e3;
        }
    }
    s0 += __shfl_xor_sync(0xffffffffu, s0, 1);
    s0 += __shfl_xor_sync(0xffffffffu, s0, 2);
    s1 += __shfl_xor_sync(0xffffffffu, s1, 1);
    s1 += __shfl_xor_sync(0xffffffffu, s1, 2);
    if (tig == 0) {
        atomicAdd(&bsum[r0], s0);
        atomicAdd(&bsum[r1], s1);
    }
    __syncthreads();
    if (tid < 64) atomicAdd(&g_rowsum[tid], bsum[tid]);
}

// ------------- word softmax + alpha scale + scatter (blocks 0-255) + norm -----
__global__ __launch_bounds__(256) void k_scatnorm(const int* __restrict__ num,
                                                  float* __restrict__ out) {
    int tid = threadIdx.x, wid = tid >> 5, lane = tid & 31;
    if (blockIdx.x < 256) {
        int pair = blockIdx.x * 8 + wid;        // 2048 (b,s) pairs
        int b = pair >> 5, s = pair & 31;
        const float* scin = g_wsc + ((size_t)b * NS + s) * NW;
        float v0 = (lane < NW) ? scin[lane] : -1e30f;
        float v1 = (lane + 32 < NW) ? scin[lane + 32] : -1e30f;
        float m = fmaxf(v0, v1);
#pragma unroll
        for (int o = 16; o; o >>= 1) m = fmaxf(m, __shfl_xor_sync(0xffffffffu, m, o));
        float e0 = (lane < NW) ? __expf(v0 - m) : 0.0f;
        float e1 = (lane + 32 < NW) ? __expf(v1 - m) : 0.0f;
        float Z = e0 + e1;
#pragma unroll
        for (int o = 16; o; o >>= 1) Z += __shfl_xor_sync(0xffffffffu, Z, o);
        float a = g_alpha[b * NS + s] / Z;
        int nbase = b * (NS * NW) + s * NW;
        if (lane < NW)
            atomicAdd(out + COPY_OFF + (size_t)b * EXT + num[nbase + lane], e0 * a);
        if (lane + 32 < NW)
            atomicAdd(out + COPY_OFF + (size_t)b * EXT + num[nbase + lane + 32], e1 * a);
    } else {
        size_t i = (size_t)(blockIdx.x - 256) * 256 + tid;
        size_t stride = (size_t)512 * 256;
        size_t total = (size_t)BB * EXT;
        for (size_t t = i; t < total; t += stride) {
            int v = (int)(t % EXT);
            if (v < VV) {
                int b = (int)(t / EXT);
                out[GEN_OFF + t] *= (1.0f / g_rowsum[b]);
            }
        }
    }
}

// =================== host ===================
extern "C" void kernel_launch(void* const* d_in, const int* in_sizes, int n_in,
                              void* d_out, int out_size) {
    const float *emb = 0, *hid = 0, *enc_s = 0, *enc_w = 0;
    const float *Wx = 0, *Wh = 0, *gb = 0, *Ws = 0, *Ww = 0;
    const float *fcW = 0, *fcb = 0, *wc = 0, *wh = 0, *wd = 0, *wi = 0;
    const int* num = 0;
    int c262 = 0, c512 = 0;
    for (int i = 0; i < n_in; i++) {
        int sz = in_sizes[i];
        const float* p = (const float*)d_in[i];
        switch (sz) {
            case 16384:    emb = p; break;
            case 32768:    hid = p; break;
            case 1048576:  enc_s = p; break;
            case 52428800: enc_w = p; break;
            case 102400:   num = (const int*)d_in[i]; break;
            case 393216:   Wx = p; break;
            case 786432:   Wh = p; break;
            case 3072:     gb = p; break;
            case 12800000: fcW = p; break;
            case 50000:    fcb = p; break;
            case 256:      wi = p; break;
            case 512:      if (c512 == 0) wc = p; else wh = p; c512++; break;
            case 262144:
                if (c262 == 0) Ws = p; else if (c262 == 1) Ww = p; else wd = p;
                c262++; break;
            default: break; // batch_size scalar
        }
    }
    float* out = (float*)d_out;

    k_small<<<SMALL_GRID, 256>>>(emb, hid, enc_s, Wx, Wh, gb, Ws, Ww, wd,
                                 wc, wh, wi, out);
    k_wscore<<<BB * NS, 256>>>(enc_w);
    k_fc<<<(VV + 127) / 128, 256>>>(fcW, fcb, out);
    k_scatnorm<<<768, 256>>>(num, out);
}

// round 9
// speedup vs baseline: 2.0904x; 1.0760x over previous
#include <cuda_runtime.h>
#include <math.h>
#include <stdint.h>

#define BB 64
#define UU 512
#define EMBD 256
#define NS 32
#define NW 50
#define VV 50000
#define EXT 50100

#define GEN_OFF   ((size_t)BB*UU)
#define COPY_OFF  (GEN_OFF + (size_t)BB*EXT)
#define PGEN_OFF  (COPY_OFF + (size_t)BB*EXT)

#define SMALL_GRID 128
#define FC_TILES 391
#define WS_UNITS (BB*NS)
#define HEAVY_GRID (FC_TILES + WS_UNITS)   // 2439

// ------------- scratch -------------
__device__ float g_xm[BB*1536];
__device__ float g_hm[BB*1536];
__device__ float g_q[BB*UU];
__device__ float g_qw[BB*UU];
__device__ float g_alpha[BB*NS];
__device__ float g_ctx[BB*UU];
__device__ float g_ht[BB*256];       // pre-tanh: htp + ctx@wd_top (atomics)
__device__ float g_rowsum[BB];
__device__ float g_wsc[BB*NS*NW];    // raw word scores
__device__ unsigned long long g_bar; // monotonic ticket barrier

// ------------- helpers -------------
__device__ __forceinline__ uint32_t f2tf32(float f) {
    uint32_t u;
    asm("cvt.rna.tf32.f32 %0, %1;" : "=r"(u) : "f"(f));
    return u;
}

__device__ __forceinline__ void mma_tf32(float& c0, float& c1, float& c2, float& c3,
                                         uint32_t a0, uint32_t a1, uint32_t a2, uint32_t a3,
                                         uint32_t b0, uint32_t b1) {
    asm volatile(
        "mma.sync.aligned.m16n8k8.row.col.f32.tf32.tf32.f32 "
        "{%0,%1,%2,%3}, {%4,%5,%6,%7}, {%8,%9}, {%0,%1,%2,%3};\n"
        : "+f"(c0), "+f"(c1), "+f"(c2), "+f"(c3)
        : "r"(a0), "r"(a1), "r"(a2), "r"(a3), "r"(b0), "r"(b1));
}

__device__ __forceinline__ void grid_bar() {
    __syncthreads();
    if (threadIdx.x == 0) {
        __threadfence();
        unsigned long long ticket = atomicAdd(&g_bar, 1ULL);
        unsigned long long target = (ticket / SMALL_GRID + 1ULL) * SMALL_GRID;
        while (*(volatile unsigned long long*)&g_bar < target) { }
        __threadfence();
    }
    __syncthreads();
}

// ------------- small GEMM tile: C[64, 32-col tile] = A[64,K] @ W[K,N] -------------
__device__ __forceinline__ void gemm_tile(float* As, float* Wt,
                                          const float* __restrict__ A, int lda,
                                          const float* __restrict__ W, int ldw,
                                          const float* __restrict__ bias,
                                          float* __restrict__ C, int ldc,
                                          int K, int blk, int atomic_out) {
    int tid = threadIdx.x;
    int c  = tid & 31;
    int rg = tid >> 5;
    int n0 = blk * 32;
    int n  = n0 + c;

    float acc[8];
#pragma unroll
    for (int r = 0; r < 8; r++) acc[r] = 0.0f;

    for (int k0 = 0; k0 < K; k0 += 32) {
        for (int i = tid; i < 2048; i += 256) {
            int k = i & 31, b = i >> 5;
            As[k * 68 + b] = A[(size_t)b * lda + k0 + k];
        }
        for (int i = tid; i < 1024; i += 256) {
            int kk = i >> 5, c2 = i & 31;
            Wt[kk * 32 + c2] = W[(size_t)(k0 + kk) * ldw + n0 + c2];
        }
        __syncthreads();
#pragma unroll 8
        for (int kk = 0; kk < 32; kk++) {
            float w = Wt[kk * 32 + c];
            float4 a0 = *(const float4*)&As[kk * 68 + rg * 8];
            float4 a1 = *(const float4*)&As[kk * 68 + rg * 8 + 4];
            acc[0] += a0.x * w; acc[1] += a0.y * w;
            acc[2] += a0.z * w; acc[3] += a0.w * w;
            acc[4] += a1.x * w; acc[5] += a1.y * w;
            acc[6] += a1.z * w; acc[7] += a1.w * w;
        }
        __syncthreads();
    }
#pragma unroll
    for (int r = 0; r < 8; r++) {
        int row = rg * 8 + r;
        if (atomic_out) {
            atomicAdd(&C[(size_t)row * ldc + n], acc[r]);
        } else {
            float bv = bias ? bias[n] : 0.0f;
            C[(size_t)row * ldc + n] = acc[r] + bv;
        }
    }
}

// ======= persistent small-chain kernel =======
__global__ __launch_bounds__(256) void k_small(const float* __restrict__ emb,
                                               const float* __restrict__ hid,
                                               const float* __restrict__ enc_s,
                                               const float* __restrict__ Wx,
                                               const float* __restrict__ Wh,
                                               const float* __restrict__ gb,
                                               const float* __restrict__ Ws,
                                               const float* __restrict__ Ww,
                                               const float* __restrict__ wd,
                                               const float* __restrict__ wc,
                                               const float* __restrict__ wh,
                                               const float* __restrict__ wi,
                                               float* __restrict__ out) {
    __shared__ __align__(16) float sm[3200];
    float* As = sm;
    float* Wt = sm + 2176;
    int bid = blockIdx.x, tid = threadIdx.x;
    int wid = tid >> 5, lane = tid & 31;

    // ---- phase 1: GRU gate GEMMs + zero copy/pad/rowsum ----
    if (bid < 48) {
        gemm_tile(As, Wt, emb, 256, Wx, 1536, gb, g_xm, 1536, 256, bid, 0);
    } else if (bid < 96) {
        gemm_tile(As, Wt, hid, 512, Wh, 1536, gb + 1536, g_hm, 1536, 512, bid - 48, 0);
    } else {
        float4 z4 = make_float4(0.f, 0.f, 0.f, 0.f);
        size_t total4 = (size_t)BB * EXT / 4;
        for (size_t t = (size_t)(bid - 96) * 256 + tid; t < total4; t += 32 * 256)
            *(float4*)(out + COPY_OFF + t * 4) = z4;
        for (int t = (bid - 96) * 256 + tid; t < BB * 100; t += 32 * 256) {
            int b = t / 100, v = t % 100;
            out[GEN_OFF + (size_t)b * EXT + VV + v] = 0.0f;
        }
        if (bid == 96 && tid < BB) g_rowsum[tid] = 0.0f;
    }
    grid_bar();

    // ---- phase 2: GRU combine -> dec ----
    {
        int idx = bid * 256 + tid;
        int b = idx >> 9, u = idx & 511;
        float xz = g_xm[b * 1536 + u];
        float xr = g_xm[b * 1536 + 512 + u];
        float xh = g_xm[b * 1536 + 1024 + u];
        float hz = g_hm[b * 1536 + u];
        float hr = g_hm[b * 1536 + 512 + u];
        float hh = g_hm[b * 1536 + 1024 + u];
        float z = 1.0f / (1.0f + __expf(-(xz + hz)));
        float r = 1.0f / (1.0f + __expf(-(xr + hr)));
        float hc = tanhf(xh + r * hh);
        out[idx] = z * hid[idx] + (1.0f - z) * hc;
    }
    grid_bar();

    // ---- phase 3: q, qw, ht_partial ----
    if (bid < 16) {
        gemm_tile(As, Wt, out, 512, Ws, 512, 0, g_q, 512, 512, bid, 0);
    } else if (bid < 32) {
        gemm_tile(As, Wt, out, 512, Ww, 512, 0, g_qw, 512, 512, bid - 16, 0);
    } else if (bid < 40) {
        gemm_tile(As, Wt, out, 512, wd + (size_t)512 * 256, 256, 0, g_ht, 256, 512, bid - 32, 0);
    }
    grid_bar();

    // ---- phase 4: sentence attention + context + p_gen ----
    if (bid < 64) {
        int b = bid;
        float* qs    = sm;
        float* dec_s = sm + 512;
        float* ctxS  = sm + 1024;
        float* sc    = sm + 1536;
        float* red   = sm + 1576;

        qs[tid] = g_q[b * 512 + tid];
        qs[tid + 256] = g_q[b * 512 + tid + 256];
        dec_s[tid] = out[b * 512 + tid];
        dec_s[tid + 256] = out[b * 512 + tid + 256];
        __syncthreads();

        const float4* qv4 = (const float4*)qs;
        for (int s = wid; s < NS; s += 8) {
            const float4* e = (const float4*)(enc_s + ((size_t)b * NS + s) * 512);
            float sum = 0.0f;
#pragma unroll
            for (int j = 0; j < 4; j++) {
                float4 ev = e[lane + 32 * j];
                float4 qv = qv4[lane + 32 * j];
                sum += ev.x * qv.x + ev.y * qv.y + ev.z * qv.z + ev.w * qv.w;
            }
#pragma unroll
            for (int o = 16; o; o >>= 1) sum += __shfl_xor_sync(0xffffffffu, sum, o);
            if (lane == 0) sc[s] = sum;
        }
        __syncthreads();
        if (wid == 0) {
            float v = sc[lane];
            float m = v;
#pragma unroll
            for (int o = 16; o; o >>= 1) m = fmaxf(m, __shfl_xor_sync(0xffffffffu, m, o));
            float e = __expf(v - m);
            float Z = e;
#pragma unroll
            for (int o = 16; o; o >>= 1) Z += __shfl_xor_sync(0xffffffffu, Z, o);
            float a = e / Z;
            sc[lane] = a;
            g_alpha[b * NS + lane] = a;
        }
        __syncthreads();
        for (int d = tid; d < 512; d += 256) {
            float s = 0.0f;
#pragma unroll 8
            for (int k = 0; k < NS; k++) s += sc[k] * enc_s[((size_t)b * NS + k) * 512 + d];
            ctxS[d] = s;
            g_ctx[b * 512 + d] = s;
        }
        __syncthreads();
        float p = ctxS[tid] * wc[tid] + ctxS[tid + 256] * wc[tid + 256];
        p += dec_s[tid] * wh[tid] + dec_s[tid + 256] * wh[tid + 256];
        p += emb[b * 256 + tid] * wi[tid];
#pragma unroll
        for (int o = 16; o; o >>= 1) p += __shfl_xor_sync(0xffffffffu, p, o);
        if (lane == 0) red[wid] = p;
        __syncthreads();
        if (tid == 0) {
            float t = 0.0f;
            for (int w = 0; w < 8; w++) t += red[w];
            out[PGEN_OFF + b] = 1.0f / (1.0f + __expf(-t));
        }
        __syncthreads();
    }
    grid_bar();

    // ---- phase 5: g_ht += ctx @ wd_top ----
    if (bid < 64) {
        int nt = bid & 7, kc = bid >> 3;
        gemm_tile(As, Wt, g_ctx + kc * 64, 512, wd + (size_t)(kc * 64) * 256, 256,
                  0, g_ht, 256, 64, nt, 1);
    }
}

// ======= heavy kernel: FC tiles interleaved with word-score units =======
// bid % 6 == 0 && bid/6 < 391  -> FC tile bid/6
// else                          -> wscore unit (continuous numbering)
__global__ __launch_bounds__(256) void k_heavy(const float* __restrict__ fcW,
                                               const float* __restrict__ fcb,
                                               const float* __restrict__ enc_w,
                                               float* __restrict__ out) {
    __shared__ __align__(16) uint32_t smu[64 * 36 + 32 * 136];
    int bid = blockIdx.x, tid = threadIdx.x;

    bool is_fc = (bid % 6 == 0) && (bid / 6 < FC_TILES);
    if (is_fc) {
        uint32_t* Hs  = smu;                 // [64][36]
        uint32_t* Wsm = smu + 64 * 36;       // [32][136]
        __shared__ float bsum[64];

        int w = tid >> 5, lane = tid & 31;
        int gid = lane >> 2, tig = lane & 3;
        int mrow = (w & 3) * 16;
        int nloc = (w >> 2) * 64;
        int n0 = (bid / 6) * 128;

        if (tid < 64) bsum[tid] = 0.0f;

        float c[8][4];
#pragma unroll
        for (int t = 0; t < 8; t++)
#pragma unroll
            for (int j = 0; j < 4; j++) c[t][j] = 0.0f;

        for (int ks = 0; ks < 8; ks++) {
            for (int u = tid; u < 512; u += 256) {
                int row = u >> 3, c4 = (u & 7) * 4;
                float4 v = *(const float4*)(g_ht + row * 256 + ks * 32 + c4);
                Hs[row * 36 + c4 + 0] = f2tf32(tanhf(v.x));
                Hs[row * 36 + c4 + 1] = f2tf32(tanhf(v.y));
                Hs[row * 36 + c4 + 2] = f2tf32(tanhf(v.z));
                Hs[row * 36 + c4 + 3] = f2tf32(tanhf(v.w));
            }
            for (int u = tid; u < 1024; u += 256) {
                int k = u >> 5, c4 = (u & 31) * 4;
                int n = n0 + c4;
                const float* src = fcW + (size_t)(ks * 32 + k) * VV + n;
                float4 v = make_float4(0.f, 0.f, 0.f, 0.f);
                if (n + 3 < VV) v = *(const float4*)src;
                else {
                    if (n     < VV) v.x = src[0];
                    if (n + 1 < VV) v.y = src[1];
                    if (n + 2 < VV) v.z = src[2];
                }
                uint4 t4;
                t4.x = f2tf32(v.x); t4.y = f2tf32(v.y);
                t4.z = f2tf32(v.z); t4.w = f2tf32(v.w);
                *(uint4*)&Wsm[k * 136 + c4] = t4;
            }
            __syncthreads();
#pragma unroll
            for (int k8 = 0; k8 < 4; k8++) {
                int kb = k8 * 8;
                uint32_t a0 = Hs[(mrow + gid) * 36 + kb + tig];
                uint32_t a1 = Hs[(mrow + gid + 8) * 36 + kb + tig];
                uint32_t a2 = Hs[(mrow + gid) * 36 + kb + tig + 4];
                uint32_t a3 = Hs[(mrow + gid + 8) * 36 + kb + tig + 4];
#pragma unroll
                for (int t = 0; t < 8; t++) {
                    uint32_t b0 = Wsm[(kb + tig) * 136 + nloc + t * 8 + gid];
                    uint32_t b1 = Wsm[(kb + tig + 4) * 136 + nloc + t * 8 + gid];
                    mma_tf32(c[t][0], c[t][1], c[t][2], c[t][3], a0, a1, a2, a3, b0, b1);
                }
            }
            __syncthreads();
        }

        float s0 = 0.0f, s1 = 0.0f;
        int r0 = mrow + gid, r1 = r0 + 8;
#pragma unroll
        for (int t = 0; t < 8; t++) {
            int col = n0 + nloc + t * 8 + 2 * tig;
            if (col < VV) {
                float b0v = fcb[col], b1v = fcb[col + 1];
                float e0 = __expf(c[t][0] + b0v);
                float e1 = __expf(c[t][1] + b1v);
                float e2 = __expf(c[t][2] + b0v);
                float e3 = __expf(c[t][3] + b1v);
                *(float2*)(out + GEN_OFF + (size_t)r0 * EXT + col) = make_float2(e0, e1);
                *(float2*)(out + GEN_OFF + (size_t)r1 * EXT + col) = make_float2(e2, e3);
                s0 += e0 + e1;
                s1 += e2 + e3;
            }
        }
        s0 += __shfl_xor_sync(0xffffffffu, s0, 1);
        s0 += __shfl_xor_sync(0xffffffffu, s0, 2);
        s1 += __shfl_xor_sync(0xffffffffu, s1, 1);
        s1 += __shfl_xor_sync(0xffffffffu, s1, 2);
        if (tig == 0) {
            atomicAdd(&bsum[r0], s0);
            atomicAdd(&bsum[r1], s1);
        }
        __syncthreads();
        if (tid < 64) atomicAdd(&g_rowsum[tid], bsum[tid]);
    } else {
        // ---- word-score unit ----
        int ws;
        if (bid >= FC_TILES * 6) ws = bid - FC_TILES;
        else                     ws = bid - bid / 6 - 1;
        int b = ws >> 5;
        int s = ws & 31;
        float* qs = (float*)smu;
        int wid = tid >> 5, lane = tid & 31;

        qs[tid] = g_qw[b * 512 + tid];
        qs[tid + 256] = g_qw[b * 512 + tid + 256];
        __syncthreads();

        const float4* qv4 = (const float4*)qs;
        const float4* ebase = (const float4*)(enc_w + ((size_t)b * NS + s) * NW * 512);
        float* scout = g_wsc + ((size_t)b * NS + s) * NW;

#pragma unroll
        for (int w0 = 0; w0 < 48; w0 += 16) {
            int wa = w0 + wid, wb = wa + 8;
            const float4* ea = ebase + (size_t)wa * 128;
            const float4* eb = ebase + (size_t)wb * 128;
            float sa = 0.0f, sb = 0.0f;
#pragma unroll
            for (int j = 0; j < 4; j++) {
                float4 qv = qv4[lane + 32 * j];
                float4 va = __ldcs(ea + lane + 32 * j);
                float4 vb = __ldcs(eb + lane + 32 * j);
                sa += va.x * qv.x + va.y * qv.y + va.z * qv.z + va.w * qv.w;
                sb += vb.x * qv.x + vb.y * qv.y + vb.z * qv.z + vb.w * qv.w;
            }
#pragma unroll
            for (int o = 16; o; o >>= 1) {
                sa += __shfl_xor_sync(0xffffffffu, sa, o);
                sb += __shfl_xor_sync(0xffffffffu, sb, o);
            }
            if (lane == 0) { scout[wa] = sa; scout[wb] = sb; }
        }
        if (wid < 2) {
            int wa = 48 + wid;
            const float4* ea = ebase + (size_t)wa * 128;
            float sa = 0.0f;
#pragma unroll
            for (int j = 0; j < 4; j++) {
                float4 qv = qv4[lane + 32 * j];
                float4 va = __ldcs(ea + lane + 32 * j);
                sa += va.x * qv.x + va.y * qv.y + va.z * qv.z + va.w * qv.w;
            }
#pragma unroll
            for (int o = 16; o; o >>= 1) sa += __shfl_xor_sync(0xffffffffu, sa, o);
            if (lane == 0) scout[wa] = sa;
        }
    }
}

// ------------- word softmax + scatter (blocks 0-255) + vectorized norm -----
__global__ __launch_bounds__(256) void k_scatnorm(const int* __restrict__ num,
                                                  float* __restrict__ out) {
    int tid = threadIdx.x, wid = tid >> 5, lane = tid & 31;
    if (blockIdx.x < 256) {
        int pair = blockIdx.x * 8 + wid;        // 2048 (b,s) pairs
        int b = pair >> 5, s = pair & 31;
        const float* scin = g_wsc + ((size_t)b * NS + s) * NW;
        float v0 = (lane < NW) ? scin[lane] : -1e30f;
        float v1 = (lane + 32 < NW) ? scin[lane + 32] : -1e30f;
        float m = fmaxf(v0, v1);
#pragma unroll
        for (int o = 16; o; o >>= 1) m = fmaxf(m, __shfl_xor_sync(0xffffffffu, m, o));
        float e0 = (lane < NW) ? __expf(v0 - m) : 0.0f;
        float e1 = (lane + 32 < NW) ? __expf(v1 - m) : 0.0f;
        float Z = e0 + e1;
#pragma unroll
        for (int o = 16; o; o >>= 1) Z += __shfl_xor_sync(0xffffffffu, Z, o);
        float a = g_alpha[b * NS + s] / Z;
        int nbase = b * (NS * NW) + s * NW;
        if (lane < NW)
            atomicAdd(out + COPY_OFF + (size_t)b * EXT + num[nbase + lane], e0 * a);
        if (lane + 32 < NW)
            atomicAdd(out + COPY_OFF + (size_t)b * EXT + num[nbase + lane + 32], e1 * a);
    } else {
        // vectorized normalize: 512 blocks; 8 segs per row, 64 rows
        int nb = blockIdx.x - 256;
        int b = nb >> 3, seg = nb & 7;
        float inv = 1.0f / g_rowsum[b];
        float4* row = (float4*)(out + GEN_OFF + (size_t)b * EXT);   // 12500 float4 of vocab
        int start = seg * 1563;
        int end = start + 1563; if (end > 12500) end = 12500;
        for (int i = start + tid; i < end; i += 256) {
            float4 v = __ldcs(row + i);
            v.x *= inv; v.y *= inv; v.z *= inv; v.w *= inv;
            __stcs(row + i, v);
        }
    }
}

// =================== host ===================
extern "C" void kernel_launch(void* const* d_in, const int* in_sizes, int n_in,
                              void* d_out, int out_size) {
    const float *emb = 0, *hid = 0, *enc_s = 0, *enc_w = 0;
    const float *Wx = 0, *Wh = 0, *gb = 0, *Ws = 0, *Ww = 0;
    const float *fcW = 0, *fcb = 0, *wc = 0, *wh = 0, *wd = 0, *wi = 0;
    const int* num = 0;
    int c262 = 0, c512 = 0;
    for (int i = 0; i < n_in; i++) {
        int sz = in_sizes[i];
        const float* p = (const float*)d_in[i];
        switch (sz) {
            case 16384:    emb = p; break;
            case 32768:    hid = p; break;
            case 1048576:  enc_s = p; break;
            case 52428800: enc_w = p; break;
            case 102400:   num = (const int*)d_in[i]; break;
            case 393216:   Wx = p; break;
            case 786432:   Wh = p; break;
            case 3072:     gb = p; break;
            case 12800000: fcW = p; break;
            case 50000:    fcb = p; break;
            case 256:      wi = p; break;
            case 512:      if (c512 == 0) wc = p; else wh = p; c512++; break;
            case 262144:
                if (c262 == 0) Ws = p; else if (c262 == 1) Ww = p; else wd = p;
                c262++; break;
            default: break; // batch_size scalar
        }
    }
    float* out = (float*)d_out;

    k_small<<<SMALL_GRID, 256>>>(emb, hid, enc_s, Wx, Wh, gb, Ws, Ww, wd,
                                 wc, wh, wi, out);
    k_heavy<<<HEAVY_GRID, 256>>>(fcW, fcb, enc_w, out);
    k_scatnorm<<<768, 256>>>(num, out);
}